// round 7
// baseline (speedup 1.0000x reference)
#include <cuda_runtime.h>
#include <cuda_bf16.h>
#include <cstdint>

// EdgeConv fused, round 7: window-variant table gather (1 LDG.128/slot, no smem
// transpose) + bf16 3-term split mma.sync GEMM (unchanged from round 6).
// out[p][o] = sum_cc E[p][cc] * Wt[cc][o] + bias[o]
//   E = [gsum | x], Wt[cc<64] = W[o][cc]/20, Wt[cc>=64] = W[o][cc]-W[o][cc-64]

#define BB 4
#define NN 32768
#define KK 20
#define CC 64
#define C2 128
#define OUTD 64
#define TP 128
#define THREADS 256
#define ROWB 256        // A/W image row bytes; swizzle k' = (k&8)|((k^row)&7)

// smem byte offsets
#define OFF_W_HI  0
#define OFF_W_LO  16384
#define OFF_A_HI  32768
#define OFF_A_LO  65536
#define OFF_BIAS  98304
#define SMEM_BYTES (OFF_BIAS + 256)    // 98560 -> 2 CTAs/SM

__device__ float g_xv[(size_t)BB * NN * 20];               // variant table 10.5 MB
__device__ __align__(16) unsigned short g_Whi[OUTD * C2];  // swizzled W images
__device__ __align__(16) unsigned short g_Wlo[OUTD * C2];

// ---------------- helpers ----------------
__device__ __forceinline__ unsigned smem_u32(const void* p) {
    unsigned a;
    asm("{ .reg .u64 t; cvta.to.shared.u64 t, %1; cvt.u32.u64 %0, t; }" : "=r"(a) : "l"(p));
    return a;
}
__device__ __forceinline__ void ldsm4(unsigned* r, unsigned addr) {
    asm volatile("ldmatrix.sync.aligned.m8n8.x4.shared.b16 {%0,%1,%2,%3}, [%4];"
                 : "=r"(r[0]), "=r"(r[1]), "=r"(r[2]), "=r"(r[3]) : "r"(addr));
}
__device__ __forceinline__ void mma16816(float* d, const unsigned* a,
                                         unsigned b0, unsigned b1) {
    asm volatile(
        "mma.sync.aligned.m16n8k16.row.col.f32.bf16.bf16.f32 "
        "{%0,%1,%2,%3}, {%4,%5,%6,%7}, {%8,%9}, {%0,%1,%2,%3};"
        : "+f"(d[0]), "+f"(d[1]), "+f"(d[2]), "+f"(d[3])
        : "r"(a[0]), "r"(a[1]), "r"(a[2]), "r"(a[3]), "r"(b0), "r"(b1));
}
__device__ __forceinline__ unsigned pack_hi(float a, float b, float& ra, float& rb) {
    __nv_bfloat16 ha = __float2bfloat16(a), hb = __float2bfloat16(b);
    ra = a - __bfloat162float(ha);
    rb = b - __bfloat162float(hb);
    return ((unsigned)__bfloat16_as_ushort(hb) << 16) | (unsigned)__bfloat16_as_ushort(ha);
}
__device__ __forceinline__ unsigned pack_lo(float ra, float rb) {
    __nv_bfloat16 la = __float2bfloat16(ra), lb = __float2bfloat16(rb);
    return ((unsigned)__bfloat16_as_ushort(lb) << 16) | (unsigned)__bfloat16_as_ushort(la);
}
__device__ __forceinline__ unsigned swz(int r, int k) {
    return (unsigned)(r * ROWB + (((k & 8) | ((k ^ r) & 7)) << 4));
}

// ---------------- prep 1: window-variant table ----------------
// Per row: s4[m] = sum x[4m..4m+4), P = inclusive prefix of s4.
// xv[row][v][k]: k<3 -> P[4-v+5k] - (k? P[4-v+5(k-1)] : 0); k==3 -> P[15]-P[14-v].
__global__ void edgeconv_xv_kernel(const float* __restrict__ x)
{
    const int tid = threadIdx.x;
    const int wid = tid >> 5;
    const int lid = tid & 31;
    const int h16 = lid & 15;
    const int rowA = blockIdx.x * 16 + wid * 2;
    const int row  = rowA + (lid >> 4);

    float4 vx = ((const float4*)x)[(size_t)row * 16 + h16];
    float P = (vx.x + vx.y) + (vx.z + vx.w);     // s4[h16]

    // inclusive prefix within each 16-lane half
    #pragma unroll
    for (int d = 1; d < 16; d <<= 1) {
        float t = __shfl_up_sync(0xffffffffu, P, d);
        if (h16 >= d) P += t;
    }

    // output index o = 4v + k for lanes 0..19
    const int v = lid >> 2;          // variant (for o = lid)
    const int k = lid & 3;
    const int hi = (k < 3) ? (4 - v + 5 * k) : 15;
    const int lo = (k == 0) ? 0 : ((k < 3) ? (4 - v + 5 * (k - 1)) : (14 - v));

    // row A (P in lanes 0-15)
    float ph = __shfl_sync(0xffffffffu, P, hi);
    float pl = __shfl_sync(0xffffffffu, P, lo);
    if (k == 0) pl = 0.0f;
    if (lid < 20) g_xv[(size_t)rowA * 20 + lid] = ph - pl;

    // row B (P in lanes 16-31)
    ph = __shfl_sync(0xffffffffu, P, 16 + hi);
    pl = __shfl_sync(0xffffffffu, P, 16 + lo);
    if (k == 0) pl = 0.0f;
    if (lid < 20) g_xv[(size_t)(rowA + 1) * 20 + lid] = ph - pl;
}

// ---------------- prep 2: combined weights -> bf16 hi/lo swizzled images ----
__global__ void edgeconv_prepw_kernel(const float* __restrict__ W)
{
    int i = blockIdx.x * blockDim.x + threadIdx.x;
    if (i < OUTD * C2) {
        int o = i >> 7, cc = i & 127;
        float w = W[o * C2 + cc];
        if (cc < CC) w *= (1.0f / (float)KK);
        else         w -= W[o * C2 + (cc - CC)];
        __nv_bfloat16 h = __float2bfloat16(w);
        __nv_bfloat16 l = __float2bfloat16(w - __bfloat162float(h));
        unsigned byteoff = swz(o, cc >> 3) + ((cc & 7) << 1);
        g_Whi[byteoff >> 1] = __bfloat16_as_ushort(h);
        g_Wlo[byteoff >> 1] = __bfloat16_as_ushort(l);
    }
}

// ---------------- main fused kernel ----------------
__global__ __launch_bounds__(THREADS, 2)
void edgeconv_fused_kernel(const float* __restrict__ x,
                           const int* __restrict__ adj,
                           const float* __restrict__ bias,
                           float* __restrict__ out)
{
    extern __shared__ __align__(16) char smem[];
    const unsigned smem_base = smem_u32(smem);

    const int tid = threadIdx.x;
    const int wid = tid >> 5;
    const int lid = tid & 31;
    const int gp0 = blockIdx.x * TP;
    const int b   = gp0 >> 15;
    const int n0  = gp0 & (NN - 1);

    // ---- copy prepped W images + bias ----
    {
        const uint4* sh = (const uint4*)g_Whi;
        const uint4* sl = (const uint4*)g_Wlo;
        uint4* dh = (uint4*)(smem + OFF_W_HI);
        uint4* dl = (uint4*)(smem + OFF_W_LO);
        #pragma unroll
        for (int i = tid; i < (OUTD * C2) / 8; i += THREADS) { dh[i] = sh[i]; dl[i] = sl[i]; }
    }
    if (tid < OUTD) ((float*)(smem + OFF_BIAS))[tid] = bias[tid];

    // ---- gather: warp owns points [16*wid, 16*wid+16) ----
    const float4* __restrict__ xv4 = (const float4*)g_xv + (size_t)b * NN * 5;
    const float2* __restrict__ xb2 = (const float2*)(x + (size_t)b * NN * CC);

    // per-lane constants
    const bool act = (lid < KK);
    const int  vS  = lid % 5;                 // my slot's variant (valid lid<20)
    // routing: window cA=2*lid, cB=2*lid+1; source slot s* = (5c)>>4
    const int cA = 2 * lid, cB = 2 * lid + 1;
    const int sA = (5 * cA) >> 4;
    const int sB = (5 * cB) >> 4;
    const int vA = sA % 5, vB = sB % 5;
    const int baseA = (vA == 0) ? (16 * sA / 5) : ((16 * sA + 4) / 5 - 1);
    const int baseB = (vB == 0) ? (16 * sB / 5) : ((16 * sB + 4) / 5 - 1);
    const int kA = cA - baseA;                // 0..3
    const int kB = cB - baseB;

    int a[16];
    #pragma unroll
    for (int pi = 0; pi < 16; ++pi) {
        int gp = gp0 + 16 * wid + pi;
        a[pi] = act ? adj[(size_t)gp * KK + lid] : 0;
    }

    float4 f = make_float4(0.f, 0.f, 0.f, 0.f);
    if (act) f = xv4[(size_t)a[0] * 5 + vS];

    #pragma unroll 1
    for (int pi = 0; pi < 16; ++pi) {
        const int p = 16 * wid + pi;

        // boundary join: s3 = f.w (+ next slot's prefix piece unless v==4)
        float nx = __shfl_down_sync(0xffffffffu, f.x, 1);
        float s3 = f.w + ((act && vS < 4) ? nx : 0.0f);

        // prefetch next point's variant vector
        float4 fn = make_float4(0.f, 0.f, 0.f, 0.f);
        if (pi < 15 && act) fn = xv4[(size_t)a[pi + 1] * 5 + vS];

        // route windows to canonical lanes (cc = 2*lid, 2*lid+1)
        float tA0 = __shfl_sync(0xffffffffu, f.x, sA);
        float tA1 = __shfl_sync(0xffffffffu, f.y, sA);
        float tA2 = __shfl_sync(0xffffffffu, f.z, sA);
        float tA3 = __shfl_sync(0xffffffffu, s3,  sA);
        float tB0 = __shfl_sync(0xffffffffu, f.x, sB);
        float tB1 = __shfl_sync(0xffffffffu, f.y, sB);
        float tB2 = __shfl_sync(0xffffffffu, f.z, sB);
        float tB3 = __shfl_sync(0xffffffffu, s3,  sB);
        float wA = (kA == 0) ? tA0 : (kA == 1) ? tA1 : (kA == 2) ? tA2 : tA3;
        float wB = (kB == 0) ? tB0 : (kB == 1) ? tB1 : (kB == 2) ? tB2 : tB3;

        float2 xv = xb2[(size_t)(n0 + p) * 32 + lid];

        float rg0, rg1, rx0, rx1;
        unsigned hp_g = pack_hi(wA, wB, rg0, rg1);
        unsigned hp_x = pack_hi(xv.x, xv.y, rx0, rx1);
        unsigned lp_g = pack_lo(rg0, rg1);
        unsigned lp_x = pack_lo(rx0, rx1);

        const int w4 = (lid & 3) << 2;
        unsigned offg = swz(p, lid >> 2)       + w4;
        unsigned offx = swz(p, 8 + (lid >> 2)) + w4;
        *(unsigned*)(smem + OFF_A_HI + offg) = hp_g;
        *(unsigned*)(smem + OFF_A_LO + offg) = lp_g;
        *(unsigned*)(smem + OFF_A_HI + offx) = hp_x;
        *(unsigned*)(smem + OFF_A_LO + offx) = lp_x;

        f = fn;
    }

    __syncthreads();

    // ---- GEMM: warps 4M x 2N, warp tile 32x32, K=128, bf16 3-product split ----
    const int mg = wid & 3;
    const int ng = wid >> 2;
    const int lrow  = (lid & 7) + 8 * ((lid >> 3) & 1);
    const int khalf = lid >> 4;

    const int rA0 = 32 * mg + lrow;
    const int rB0 = 32 * ng + (lid & 15);

    float d[2][4][4];
    #pragma unroll
    for (int mt = 0; mt < 2; ++mt)
        #pragma unroll
        for (int nt = 0; nt < 4; ++nt)
            #pragma unroll
            for (int e = 0; e < 4; ++e) d[mt][nt][e] = 0.0f;

    #pragma unroll 2
    for (int ks = 0; ks < 8; ++ks) {
        const int k = 2 * ks + khalf;
        const unsigned a0 = smem_base + OFF_A_HI + swz(rA0, k);
        const unsigned a1 = smem_base + OFF_A_HI + swz(rA0 + 16, k);
        const unsigned b0 = smem_base + OFF_W_HI + swz(rB0, k);
        const unsigned b1 = smem_base + OFF_W_HI + swz(rB0 + 16, k);

        unsigned ah[2][4], al[2][4];
        ldsm4(ah[0], a0);
        ldsm4(ah[1], a1);
        ldsm4(al[0], a0 + (OFF_A_LO - OFF_A_HI));
        ldsm4(al[1], a1 + (OFF_A_LO - OFF_A_HI));

        unsigned bh01[4], bh23[4], bl01[4], bl23[4];
        ldsm4(bh01, b0);
        ldsm4(bh23, b1);
        ldsm4(bl01, b0 + (OFF_W_LO - OFF_W_HI));
        ldsm4(bl23, b1 + (OFF_W_LO - OFF_W_HI));

        unsigned bhf[4][2] = {{bh01[0], bh01[2]}, {bh01[1], bh01[3]},
                              {bh23[0], bh23[2]}, {bh23[1], bh23[3]}};
        unsigned blf[4][2] = {{bl01[0], bl01[2]}, {bl01[1], bl01[3]},
                              {bl23[0], bl23[2]}, {bl23[1], bl23[3]}};

        #pragma unroll
        for (int mt = 0; mt < 2; ++mt) {
            #pragma unroll
            for (int nt = 0; nt < 4; ++nt) {
                mma16816(d[mt][nt], ah[mt], bhf[nt][0], bhf[nt][1]);
                mma16816(d[mt][nt], al[mt], bhf[nt][0], bhf[nt][1]);
                mma16816(d[mt][nt], ah[mt], blf[nt][0], blf[nt][1]);
            }
        }
    }

    // ---- epilogue: bias + store ----
    const float* sBias = (const float*)(smem + OFF_BIAS);
    const int g  = lid >> 2;
    const int oc = 2 * (lid & 3);
    #pragma unroll
    for (int mt = 0; mt < 2; ++mt) {
        const int prow = gp0 + 32 * mg + 16 * mt + g;
        #pragma unroll
        for (int nt = 0; nt < 4; ++nt) {
            const int o = 32 * ng + 8 * nt + oc;
            float2 bb = *(const float2*)&sBias[o];
            float2 r0, r1;
            r0.x = d[mt][nt][0] + bb.x;  r0.y = d[mt][nt][1] + bb.y;
            r1.x = d[mt][nt][2] + bb.x;  r1.y = d[mt][nt][3] + bb.y;
            *(float2*)&out[(size_t)prow * OUTD + o]       = r0;
            *(float2*)&out[(size_t)(prow + 8) * OUTD + o] = r1;
        }
    }
}

extern "C" void kernel_launch(void* const* d_in, const int* in_sizes, int n_in,
                              void* d_out, int out_size)
{
    (void)in_sizes; (void)n_in; (void)out_size;
    const float* x    = (const float*)d_in[0];
    const int*   adj  = (const int*)d_in[1];
    const float* W    = (const float*)d_in[2];
    const float* bias = (const float*)d_in[3];
    float* out = (float*)d_out;

    cudaFuncSetAttribute(edgeconv_fused_kernel,
                         cudaFuncAttributeMaxDynamicSharedMemorySize, SMEM_BYTES);

    edgeconv_xv_kernel<<<(BB * NN) / 16, 256>>>(x);
    edgeconv_prepw_kernel<<<32, 256>>>(W);
    const int tiles = (BB * NN) / TP;   // 1024
    edgeconv_fused_kernel<<<tiles, THREADS, SMEM_BYTES>>>(x, adj, bias, out);
}

// round 8
// speedup vs baseline: 1.1414x; 1.1414x over previous
#include <cuda_runtime.h>
#include <cuda_bf16.h>
#include <cstdint>

// EdgeConv fused, round 8: compact window-variant table (1 LDG.128/slot) +
// two-plane smem scatter (no shuffles) + bf16 3-term split mma.sync GEMM.
// out[p][o] = sum_cc E[p][cc] * Wt[cc][o] + bias[o]
//   E = [gsum | x], Wt[cc<64] = W[o][cc]/20, Wt[cc>=64] = W[o][cc]-W[o][cc-64]

#define BB 4
#define NN 32768
#define KK 20
#define CC 64
#define C2 128
#define OUTD 64
#define TP 128
#define THREADS 256
#define ROWB 256        // A/W image row bytes; swizzle k' = (k&8)|((k^row)&7)

// smem byte offsets
#define OFF_W_HI  0
#define OFF_W_LO  16384
#define OFF_A_HI  32768
#define OFF_A_LO  65536
#define OFF_SCR   98304           // 8 warps x 256 floats (2 bufs x [A:64|B:64])
#define OFF_BIAS  106496
#define SMEM_BYTES (OFF_BIAS + 256)   // 106752 -> 2 CTAs/SM

__device__ float g_xv[(size_t)BB * NN * 20];               // variant table 10.5 MB
__device__ __align__(16) unsigned short g_Whi[OUTD * C2];  // swizzled W images
__device__ __align__(16) unsigned short g_Wlo[OUTD * C2];

// ---------------- helpers ----------------
__device__ __forceinline__ unsigned smem_u32(const void* p) {
    unsigned a;
    asm("{ .reg .u64 t; cvta.to.shared.u64 t, %1; cvt.u32.u64 %0, t; }" : "=r"(a) : "l"(p));
    return a;
}
__device__ __forceinline__ void ldsm4(unsigned* r, unsigned addr) {
    asm volatile("ldmatrix.sync.aligned.m8n8.x4.shared.b16 {%0,%1,%2,%3}, [%4];"
                 : "=r"(r[0]), "=r"(r[1]), "=r"(r[2]), "=r"(r[3]) : "r"(addr));
}
__device__ __forceinline__ void mma16816(float* d, const unsigned* a,
                                         unsigned b0, unsigned b1) {
    asm volatile(
        "mma.sync.aligned.m16n8k16.row.col.f32.bf16.bf16.f32 "
        "{%0,%1,%2,%3}, {%4,%5,%6,%7}, {%8,%9}, {%0,%1,%2,%3};"
        : "+f"(d[0]), "+f"(d[1]), "+f"(d[2]), "+f"(d[3])
        : "r"(a[0]), "r"(a[1]), "r"(a[2]), "r"(a[3]), "r"(b0), "r"(b1));
}
__device__ __forceinline__ unsigned pack_hi(float a, float b, float& ra, float& rb) {
    __nv_bfloat16 ha = __float2bfloat16(a), hb = __float2bfloat16(b);
    ra = a - __bfloat162float(ha);
    rb = b - __bfloat162float(hb);
    return ((unsigned)__bfloat16_as_ushort(hb) << 16) | (unsigned)__bfloat16_as_ushort(ha);
}
__device__ __forceinline__ unsigned pack_lo(float ra, float rb) {
    __nv_bfloat16 la = __float2bfloat16(ra), lb = __float2bfloat16(lb = rb);
    return ((unsigned)__bfloat16_as_ushort(lb) << 16) | (unsigned)__bfloat16_as_ushort(la);
}
__device__ __forceinline__ unsigned swz(int r, int k) {
    return (unsigned)(r * ROWB + (((k & 8) | ((k ^ r) & 7)) << 4));
}

// ---------------- prep 1: window-variant table (thread per row) ----------------
// P = inclusive prefix of the row's 16 4-chunk sums.
// xv[row][v] = { P[4-v], P[9-v]-P[4-v], P[14-v]-P[9-v], P[15]-P[14-v] }
__global__ void edgeconv_xv_kernel(const float* __restrict__ x)
{
    const int row = blockIdx.x * blockDim.x + threadIdx.x;
    const float4* __restrict__ x4 = (const float4*)x;

    float P[16];
    float run = 0.0f;
    #pragma unroll
    for (int i = 0; i < 16; ++i) {
        float4 v = x4[(size_t)row * 16 + i];
        run += (v.x + v.y) + (v.z + v.w);
        P[i] = run;
    }

    float4* __restrict__ outp = (float4*)(g_xv + (size_t)row * 20);
    #pragma unroll
    for (int v = 0; v < 5; ++v) {
        float4 o;
        o.x = P[4 - v];
        o.y = P[9 - v]  - P[4 - v];
        o.z = P[14 - v] - P[9 - v];
        o.w = P[15]     - P[14 - v];
        outp[v] = o;
    }
}

// ---------------- prep 2: combined weights -> bf16 hi/lo swizzled images ----
__global__ void edgeconv_prepw_kernel(const float* __restrict__ W)
{
    int i = blockIdx.x * blockDim.x + threadIdx.x;
    if (i < OUTD * C2) {
        int o = i >> 7, cc = i & 127;
        float w = W[o * C2 + cc];
        if (cc < CC) w *= (1.0f / (float)KK);
        else         w -= W[o * C2 + (cc - CC)];
        __nv_bfloat16 h = __float2bfloat16(w);
        __nv_bfloat16 l = __float2bfloat16(w - __bfloat162float(h));
        unsigned byteoff = swz(o, cc >> 3) + ((cc & 7) << 1);
        g_Whi[byteoff >> 1] = __bfloat16_as_ushort(h);
        g_Wlo[byteoff >> 1] = __bfloat16_as_ushort(l);
    }
}

// ---------------- main fused kernel ----------------
__global__ __launch_bounds__(THREADS, 2)
void edgeconv_fused_kernel(const float* __restrict__ x,
                           const int* __restrict__ adj,
                           const float* __restrict__ bias,
                           float* __restrict__ out)
{
    extern __shared__ __align__(16) char smem[];
    const unsigned smem_base = smem_u32(smem);

    const int tid = threadIdx.x;
    const int wid = tid >> 5;
    const int lid = tid & 31;
    const int gp0 = blockIdx.x * TP;
    const int b   = gp0 >> 15;
    const int n0  = gp0 & (NN - 1);

    // ---- copy prepped W images + bias; zero scatter planes ----
    {
        const uint4* sh = (const uint4*)g_Whi;
        const uint4* sl = (const uint4*)g_Wlo;
        uint4* dh = (uint4*)(smem + OFF_W_HI);
        uint4* dl = (uint4*)(smem + OFF_W_LO);
        #pragma unroll
        for (int i = tid; i < (OUTD * C2) / 8; i += THREADS) { dh[i] = sh[i]; dl[i] = sl[i]; }
    }
    if (tid < OUTD) ((float*)(smem + OFF_BIAS))[tid] = bias[tid];

    float* __restrict__ sw = (float*)(smem + OFF_SCR) + wid * 256;
    #pragma unroll
    for (int i = lid; i < 256; i += 32) sw[i] = 0.0f;   // zero planes (B stays 0 for
    __syncwarp();                                       //  non-boundary windows)

    // ---- gather: warp owns points [16*wid, 16*wid+16) ----
    const float4* __restrict__ xv4 = (const float4*)g_xv + (size_t)b * NN * 5;
    const float2* __restrict__ xb2 = (const float2*)(x + (size_t)b * NN * CC);

    const bool act = (lid < KK);
    const int  vS  = act ? (lid % 5) : 0;
    const int  c0  = act ? ((16 * lid - vS) / 5) : 0;     // first window of slot
    const int  a3  = ((vS == 4) ? 0 : 64) + c0 + 3;       // k=3 target (A or B plane)

    int a[16];
    #pragma unroll
    for (int pi = 0; pi < 16; ++pi) {
        int gp = gp0 + 16 * wid + pi;
        a[pi] = act ? adj[(size_t)gp * KK + lid] : 0;
    }

    float4 f = make_float4(0.f, 0.f, 0.f, 0.f);
    if (act) f = xv4[(size_t)a[0] * 5 + vS];

    #pragma unroll 1
    for (int pi = 0; pi < 16; ++pi) {
        const int p = 16 * wid + pi;
        float* buf = sw + (pi & 1) * 128;

        if (act) {
            buf[c0]     = f.x;     // complete / tail pieces -> plane A
            buf[c0 + 1] = f.y;
            buf[c0 + 2] = f.z;
            buf[a3]     = f.w;     // head piece -> plane B (or A when v==4)
        }

        float4 fn = make_float4(0.f, 0.f, 0.f, 0.f);
        if (pi < 15 && act) fn = xv4[(size_t)a[pi + 1] * 5 + vS];

        __syncwarp();

        float2 ga = *(const float2*)&buf[2 * lid];        // plane A
        float2 gb = *(const float2*)&buf[64 + 2 * lid];   // plane B (0 if complete)
        float wA = ga.x + gb.x;
        float wB = ga.y + gb.y;

        float2 xv = xb2[(size_t)(n0 + p) * 32 + lid];

        float rg0, rg1, rx0, rx1;
        unsigned hp_g = pack_hi(wA, wB, rg0, rg1);
        unsigned hp_x = pack_hi(xv.x, xv.y, rx0, rx1);
        unsigned lp_g = pack_lo(rg0, rg1);
        unsigned lp_x = pack_lo(rx0, rx1);

        const int w4 = (lid & 3) << 2;
        unsigned offg = swz(p, lid >> 2)       + w4;
        unsigned offx = swz(p, 8 + (lid >> 2)) + w4;
        *(unsigned*)(smem + OFF_A_HI + offg) = hp_g;
        *(unsigned*)(smem + OFF_A_LO + offg) = lp_g;
        *(unsigned*)(smem + OFF_A_HI + offx) = hp_x;
        *(unsigned*)(smem + OFF_A_LO + offx) = lp_x;

        f = fn;
    }

    __syncthreads();

    // ---- GEMM: warps 4M x 2N, warp tile 32x32, K=128, bf16 3-product split ----
    const int mg = wid & 3;
    const int ng = wid >> 2;
    const int lrow  = (lid & 7) + 8 * ((lid >> 3) & 1);
    const int khalf = lid >> 4;

    const int rA0 = 32 * mg + lrow;
    const int rB0 = 32 * ng + (lid & 15);

    float d[2][4][4];
    #pragma unroll
    for (int mt = 0; mt < 2; ++mt)
        #pragma unroll
        for (int nt = 0; nt < 4; ++nt)
            #pragma unroll
            for (int e = 0; e < 4; ++e) d[mt][nt][e] = 0.0f;

    #pragma unroll 2
    for (int ks = 0; ks < 8; ++ks) {
        const int k = 2 * ks + khalf;
        const unsigned a0 = smem_base + OFF_A_HI + swz(rA0, k);
        const unsigned a1 = smem_base + OFF_A_HI + swz(rA0 + 16, k);
        const unsigned b0 = smem_base + OFF_W_HI + swz(rB0, k);
        const unsigned b1 = smem_base + OFF_W_HI + swz(rB0 + 16, k);

        unsigned ah[2][4], al[2][4];
        ldsm4(ah[0], a0);
        ldsm4(ah[1], a1);
        ldsm4(al[0], a0 + (OFF_A_LO - OFF_A_HI));
        ldsm4(al[1], a1 + (OFF_A_LO - OFF_A_HI));

        unsigned bh01[4], bh23[4], bl01[4], bl23[4];
        ldsm4(bh01, b0);
        ldsm4(bh23, b1);
        ldsm4(bl01, b0 + (OFF_W_LO - OFF_W_HI));
        ldsm4(bl23, b1 + (OFF_W_LO - OFF_W_HI));

        unsigned bhf[4][2] = {{bh01[0], bh01[2]}, {bh01[1], bh01[3]},
                              {bh23[0], bh23[2]}, {bh23[1], bh23[3]}};
        unsigned blf[4][2] = {{bl01[0], bl01[2]}, {bl01[1], bl01[3]},
                              {bl23[0], bl23[2]}, {bl23[1], bl23[3]}};

        #pragma unroll
        for (int mt = 0; mt < 2; ++mt) {
            #pragma unroll
            for (int nt = 0; nt < 4; ++nt) {
                mma16816(d[mt][nt], ah[mt], bhf[nt][0], bhf[nt][1]);
                mma16816(d[mt][nt], al[mt], bhf[nt][0], bhf[nt][1]);
                mma16816(d[mt][nt], ah[mt], blf[nt][0], blf[nt][1]);
            }
        }
    }

    // ---- epilogue: bias + store ----
    const float* sBias = (const float*)(smem + OFF_BIAS);
    const int g  = lid >> 2;
    const int oc = 2 * (lid & 3);
    #pragma unroll
    for (int mt = 0; mt < 2; ++mt) {
        const int prow = gp0 + 32 * mg + 16 * mt + g;
        #pragma unroll
        for (int nt = 0; nt < 4; ++nt) {
            const int o = 32 * ng + 8 * nt + oc;
            float2 bb = *(const float2*)&sBias[o];
            float2 r0, r1;
            r0.x = d[mt][nt][0] + bb.x;  r0.y = d[mt][nt][1] + bb.y;
            r1.x = d[mt][nt][2] + bb.x;  r1.y = d[mt][nt][3] + bb.y;
            *(float2*)&out[(size_t)prow * OUTD + o]       = r0;
            *(float2*)&out[(size_t)(prow + 8) * OUTD + o] = r1;
        }
    }
}

extern "C" void kernel_launch(void* const* d_in, const int* in_sizes, int n_in,
                              void* d_out, int out_size)
{
    (void)in_sizes; (void)n_in; (void)out_size;
    const float* x    = (const float*)d_in[0];
    const int*   adj  = (const int*)d_in[1];
    const float* W    = (const float*)d_in[2];
    const float* bias = (const float*)d_in[3];
    float* out = (float*)d_out;

    cudaFuncSetAttribute(edgeconv_fused_kernel,
                         cudaFuncAttributeMaxDynamicSharedMemorySize, SMEM_BYTES);

    edgeconv_xv_kernel<<<(BB * NN) / 256, 256>>>(x);
    edgeconv_prepw_kernel<<<32, 256>>>(W);
    const int tiles = (BB * NN) / TP;   // 1024
    edgeconv_fused_kernel<<<tiles, THREADS, SMEM_BYTES>>>(x, adj, bias, out);
}

// round 9
// speedup vs baseline: 1.2249x; 1.0732x over previous
#include <cuda_runtime.h>
#include <cuda_bf16.h>
#include <cstdint>

// EdgeConv fused, round 9: coalesced smem-staged xv prep + R8 main kernel
// (plane-scatter gather, bf16 3-term split mma.sync GEMM) with x prefetch.
// out[p][o] = sum_cc E[p][cc] * Wt[cc][o] + bias[o]
//   E = [gsum | x], Wt[cc<64] = W[o][cc]/20, Wt[cc>=64] = W[o][cc]-W[o][cc-64]

#define BB 4
#define NN 32768
#define KK 20
#define CC 64
#define C2 128
#define OUTD 64
#define TP 128
#define THREADS 256
#define ROWB 256        // A/W image row bytes; swizzle k' = (k&8)|((k^row)&7)

// smem byte offsets (main kernel)
#define OFF_W_HI  0
#define OFF_W_LO  16384
#define OFF_A_HI  32768
#define OFF_A_LO  65536
#define OFF_SCR   98304           // 8 warps x 256 floats (2 bufs x [A:64|B:64])
#define OFF_BIAS  106496
#define SMEM_BYTES (OFF_BIAS + 256)   // 106752 -> 2 CTAs/SM

__device__ float g_xv[(size_t)BB * NN * 20];               // variant table 10.5 MB
__device__ __align__(16) unsigned short g_Whi[OUTD * C2];  // swizzled W images
__device__ __align__(16) unsigned short g_Wlo[OUTD * C2];

// ---------------- helpers ----------------
__device__ __forceinline__ unsigned smem_u32(const void* p) {
    unsigned a;
    asm("{ .reg .u64 t; cvta.to.shared.u64 t, %1; cvt.u32.u64 %0, t; }" : "=r"(a) : "l"(p));
    return a;
}
__device__ __forceinline__ void ldsm4(unsigned* r, unsigned addr) {
    asm volatile("ldmatrix.sync.aligned.m8n8.x4.shared.b16 {%0,%1,%2,%3}, [%4];"
                 : "=r"(r[0]), "=r"(r[1]), "=r"(r[2]), "=r"(r[3]) : "r"(addr));
}
__device__ __forceinline__ void mma16816(float* d, const unsigned* a,
                                         unsigned b0, unsigned b1) {
    asm volatile(
        "mma.sync.aligned.m16n8k16.row.col.f32.bf16.bf16.f32 "
        "{%0,%1,%2,%3}, {%4,%5,%6,%7}, {%8,%9}, {%0,%1,%2,%3};"
        : "+f"(d[0]), "+f"(d[1]), "+f"(d[2]), "+f"(d[3])
        : "r"(a[0]), "r"(a[1]), "r"(a[2]), "r"(a[3]), "r"(b0), "r"(b1));
}
__device__ __forceinline__ unsigned pack_hi(float a, float b, float& ra, float& rb) {
    __nv_bfloat16 ha = __float2bfloat16(a), hb = __float2bfloat16(b);
    ra = a - __bfloat162float(ha);
    rb = b - __bfloat162float(hb);
    return ((unsigned)__bfloat16_as_ushort(hb) << 16) | (unsigned)__bfloat16_as_ushort(ha);
}
__device__ __forceinline__ unsigned pack_lo(float ra, float rb) {
    __nv_bfloat16 la = __float2bfloat16(ra);
    __nv_bfloat16 lb = __float2bfloat16(rb);
    return ((unsigned)__bfloat16_as_ushort(lb) << 16) | (unsigned)__bfloat16_as_ushort(la);
}
__device__ __forceinline__ unsigned swz(int r, int k) {
    return (unsigned)(r * ROWB + (((k & 8) | ((k ^ r) & 7)) << 4));
}

// ---------------- prep 1: window-variant table, smem-staged & coalesced --------
// xv[row][v] = { P[4-v], P[9-v]-P[4-v], P[14-v]-P[9-v], P[15]-P[14-v] },
// P = inclusive prefix of the row's 16 4-chunk sums.
__global__ __launch_bounds__(256)
void edgeconv_xv_kernel(const float* __restrict__ x)
{
    __shared__ float s4[64 * 16];
    const int tid = threadIdx.x;
    const int R0  = blockIdx.x * 64;           // 64 rows per block

    // phase 1: coalesced: 1024 float4 reads -> 1024 s4 entries
    const float4* __restrict__ x4 = (const float4*)x + (size_t)R0 * 16;
    #pragma unroll
    for (int i = 0; i < 4; ++i) {
        int idx = tid + 256 * i;
        float4 v = x4[idx];
        s4[idx] = (v.x + v.y) + (v.z + v.w);
    }
    __syncthreads();

    // phase 2: 320 items = (row, variant); thread t does item t (+ item 256+t if t<64)
    #pragma unroll
    for (int pass = 0; pass < 2; ++pass) {
        int item = tid + pass * 256;
        if (item < 320) {
            int r = item / 5;
            int v = item - 5 * r;
            const float* s = &s4[r * 16];
            const int i1 = 4 - v, i2 = 9 - v, i3 = 14 - v;
            float cum = 0.0f, P1 = 0.0f, P2 = 0.0f, P3 = 0.0f;
            #pragma unroll
            for (int i = 0; i < 16; ++i) {
                cum += s[i];
                if (i == i1) P1 = cum;
                if (i == i2) P2 = cum;
                if (i == i3) P3 = cum;
            }
            float4 o;
            o.x = P1;
            o.y = P2 - P1;
            o.z = P3 - P2;
            o.w = cum - P3;
            *(float4*)&g_xv[(size_t)(R0 + r) * 20 + 4 * v] = o;
        }
    }
}

// ---------------- prep 2: combined weights -> bf16 hi/lo swizzled images ----
__global__ void edgeconv_prepw_kernel(const float* __restrict__ W)
{
    int i = blockIdx.x * blockDim.x + threadIdx.x;
    if (i < OUTD * C2) {
        int o = i >> 7, cc = i & 127;
        float w = W[o * C2 + cc];
        if (cc < CC) w *= (1.0f / (float)KK);
        else         w -= W[o * C2 + (cc - CC)];
        __nv_bfloat16 h = __float2bfloat16(w);
        __nv_bfloat16 l = __float2bfloat16(w - __bfloat162float(h));
        unsigned byteoff = swz(o, cc >> 3) + ((cc & 7) << 1);
        g_Whi[byteoff >> 1] = __bfloat16_as_ushort(h);
        g_Wlo[byteoff >> 1] = __bfloat16_as_ushort(l);
    }
}

// ---------------- main fused kernel ----------------
__global__ __launch_bounds__(THREADS, 2)
void edgeconv_fused_kernel(const float* __restrict__ x,
                           const int* __restrict__ adj,
                           const float* __restrict__ bias,
                           float* __restrict__ out)
{
    extern __shared__ __align__(16) char smem[];
    const unsigned smem_base = smem_u32(smem);

    const int tid = threadIdx.x;
    const int wid = tid >> 5;
    const int lid = tid & 31;
    const int gp0 = blockIdx.x * TP;
    const int b   = gp0 >> 15;
    const int n0  = gp0 & (NN - 1);

    // ---- copy prepped W images + bias; zero scatter planes ----
    {
        const uint4* sh = (const uint4*)g_Whi;
        const uint4* sl = (const uint4*)g_Wlo;
        uint4* dh = (uint4*)(smem + OFF_W_HI);
        uint4* dl = (uint4*)(smem + OFF_W_LO);
        #pragma unroll
        for (int i = tid; i < (OUTD * C2) / 8; i += THREADS) { dh[i] = sh[i]; dl[i] = sl[i]; }
    }
    if (tid < OUTD) ((float*)(smem + OFF_BIAS))[tid] = bias[tid];

    float* __restrict__ sw = (float*)(smem + OFF_SCR) + wid * 256;
    #pragma unroll
    for (int i = lid; i < 256; i += 32) sw[i] = 0.0f;   // plane B stays 0 where unused
    __syncwarp();

    // ---- gather: warp owns points [16*wid, 16*wid+16) ----
    const float4* __restrict__ xv4 = (const float4*)g_xv + (size_t)b * NN * 5;
    const float2* __restrict__ xb2 = (const float2*)(x + (size_t)b * NN * CC);

    const bool act = (lid < KK);
    const int  vS  = act ? (lid % 5) : 0;
    const int  c0  = act ? ((16 * lid - vS) / 5) : 0;     // first window of slot
    const int  a3  = ((vS == 4) ? 0 : 64) + c0 + 3;       // k=3 target (A or B plane)

    int a[16];
    #pragma unroll
    for (int pi = 0; pi < 16; ++pi) {
        int gp = gp0 + 16 * wid + pi;
        a[pi] = act ? adj[(size_t)gp * KK + lid] : 0;
    }

    float4 f = make_float4(0.f, 0.f, 0.f, 0.f);
    if (act) f = xv4[(size_t)a[0] * 5 + vS];
    float2 xc = xb2[(size_t)(n0 + 16 * wid) * 32 + lid];

    #pragma unroll 1
    for (int pi = 0; pi < 16; ++pi) {
        const int p = 16 * wid + pi;
        float* buf = sw + (pi & 1) * 128;

        if (act) {
            buf[c0]     = f.x;     // complete / tail pieces -> plane A
            buf[c0 + 1] = f.y;
            buf[c0 + 2] = f.z;
            buf[a3]     = f.w;     // head piece -> plane B (or A when v==4)
        }

        // prefetch next point's table row + center x
        float4 fn = make_float4(0.f, 0.f, 0.f, 0.f);
        float2 xn = make_float2(0.f, 0.f);
        if (pi < 15) {
            if (act) fn = xv4[(size_t)a[pi + 1] * 5 + vS];
            xn = xb2[(size_t)(n0 + p + 1) * 32 + lid];
        }

        __syncwarp();

        float2 ga = *(const float2*)&buf[2 * lid];        // plane A
        float2 gb = *(const float2*)&buf[64 + 2 * lid];   // plane B (0 if complete)
        float wA = ga.x + gb.x;
        float wB = ga.y + gb.y;

        float rg0, rg1, rx0, rx1;
        unsigned hp_g = pack_hi(wA, wB, rg0, rg1);
        unsigned hp_x = pack_hi(xc.x, xc.y, rx0, rx1);
        unsigned lp_g = pack_lo(rg0, rg1);
        unsigned lp_x = pack_lo(rx0, rx1);

        const int w4 = (lid & 3) << 2;
        unsigned offg = swz(p, lid >> 2)       + w4;
        unsigned offx = swz(p, 8 + (lid >> 2)) + w4;
        *(unsigned*)(smem + OFF_A_HI + offg) = hp_g;
        *(unsigned*)(smem + OFF_A_LO + offg) = lp_g;
        *(unsigned*)(smem + OFF_A_HI + offx) = hp_x;
        *(unsigned*)(smem + OFF_A_LO + offx) = lp_x;

        f = fn;
        xc = xn;
    }

    __syncthreads();

    // ---- GEMM: warps 4M x 2N, warp tile 32x32, K=128, bf16 3-product split ----
    const int mg = wid & 3;
    const int ng = wid >> 2;
    const int lrow  = (lid & 7) + 8 * ((lid >> 3) & 1);
    const int khalf = lid >> 4;

    const int rA0 = 32 * mg + lrow;
    const int rB0 = 32 * ng + (lid & 15);

    float d[2][4][4];
    #pragma unroll
    for (int mt = 0; mt < 2; ++mt)
        #pragma unroll
        for (int nt = 0; nt < 4; ++nt)
            #pragma unroll
            for (int e = 0; e < 4; ++e) d[mt][nt][e] = 0.0f;

    #pragma unroll 2
    for (int ks = 0; ks < 8; ++ks) {
        const int k = 2 * ks + khalf;
        const unsigned a0 = smem_base + OFF_A_HI + swz(rA0, k);
        const unsigned a1 = smem_base + OFF_A_HI + swz(rA0 + 16, k);
        const unsigned b0 = smem_base + OFF_W_HI + swz(rB0, k);
        const unsigned b1 = smem_base + OFF_W_HI + swz(rB0 + 16, k);

        unsigned ah[2][4], al[2][4];
        ldsm4(ah[0], a0);
        ldsm4(ah[1], a1);
        ldsm4(al[0], a0 + (OFF_A_LO - OFF_A_HI));
        ldsm4(al[1], a1 + (OFF_A_LO - OFF_A_HI));

        unsigned bh01[4], bh23[4], bl01[4], bl23[4];
        ldsm4(bh01, b0);
        ldsm4(bh23, b1);
        ldsm4(bl01, b0 + (OFF_W_LO - OFF_W_HI));
        ldsm4(bl23, b1 + (OFF_W_LO - OFF_W_HI));

        unsigned bhf[4][2] = {{bh01[0], bh01[2]}, {bh01[1], bh01[3]},
                              {bh23[0], bh23[2]}, {bh23[1], bh23[3]}};
        unsigned blf[4][2] = {{bl01[0], bl01[2]}, {bl01[1], bl01[3]},
                              {bl23[0], bl23[2]}, {bl23[1], bl23[3]}};

        #pragma unroll
        for (int mt = 0; mt < 2; ++mt) {
            #pragma unroll
            for (int nt = 0; nt < 4; ++nt) {
                mma16816(d[mt][nt], ah[mt], bhf[nt][0], bhf[nt][1]);
                mma16816(d[mt][nt], al[mt], bhf[nt][0], bhf[nt][1]);
                mma16816(d[mt][nt], ah[mt], blf[nt][0], blf[nt][1]);
            }
        }
    }

    // ---- epilogue: bias + store ----
    const float* sBias = (const float*)(smem + OFF_BIAS);
    const int g  = lid >> 2;
    const int oc = 2 * (lid & 3);
    #pragma unroll
    for (int mt = 0; mt < 2; ++mt) {
        const int prow = gp0 + 32 * mg + 16 * mt + g;
        #pragma unroll
        for (int nt = 0; nt < 4; ++nt) {
            const int o = 32 * ng + 8 * nt + oc;
            float2 bb = *(const float2*)&sBias[o];
            float2 r0, r1;
            r0.x = d[mt][nt][0] + bb.x;  r0.y = d[mt][nt][1] + bb.y;
            r1.x = d[mt][nt][2] + bb.x;  r1.y = d[mt][nt][3] + bb.y;
            *(float2*)&out[(size_t)prow * OUTD + o]       = r0;
            *(float2*)&out[(size_t)(prow + 8) * OUTD + o] = r1;
        }
    }
}

extern "C" void kernel_launch(void* const* d_in, const int* in_sizes, int n_in,
                              void* d_out, int out_size)
{
    (void)in_sizes; (void)n_in; (void)out_size;
    const float* x    = (const float*)d_in[0];
    const int*   adj  = (const int*)d_in[1];
    const float* W    = (const float*)d_in[2];
    const float* bias = (const float*)d_in[3];
    float* out = (float*)d_out;

    cudaFuncSetAttribute(edgeconv_fused_kernel,
                         cudaFuncAttributeMaxDynamicSharedMemorySize, SMEM_BYTES);

    edgeconv_xv_kernel<<<(BB * NN) / 64, 256>>>(x);
    edgeconv_prepw_kernel<<<32, 256>>>(W);
    const int tiles = (BB * NN) / TP;   // 1024
    edgeconv_fused_kernel<<<tiles, THREADS, SMEM_BYTES>>>(x, adj, bias, out);
}

// round 10
// speedup vs baseline: 1.3927x; 1.1370x over previous
#include <cuda_runtime.h>
#include <cuda_bf16.h>
#include <cstdint>

// EdgeConv fused, round 10: pair-unrolled gather (2-point prefetch lead, 4
// scattered LDG.128 in flight) + plane-scatter transpose + bf16 3-term split
// mma.sync GEMM. Preps unchanged from round 9.
// out[p][o] = sum_cc E[p][cc] * Wt[cc][o] + bias[o]
//   E = [gsum | x], Wt[cc<64] = W[o][cc]/20, Wt[cc>=64] = W[o][cc]-W[o][cc-64]

#define BB 4
#define NN 32768
#define KK 20
#define CC 64
#define C2 128
#define OUTD 64
#define TP 128
#define THREADS 256
#define ROWB 256        // A/W image row bytes; swizzle k' = (k&8)|((k^row)&7)

// smem byte offsets (main kernel)
#define OFF_W_HI  0
#define OFF_W_LO  16384
#define OFF_A_HI  32768
#define OFF_A_LO  65536
#define OFF_SCR   98304           // 8 warps x 256 floats (2 bufs x [A:64|B:64])
#define OFF_BIAS  106496
#define SMEM_BYTES (OFF_BIAS + 256)   // 106752 -> 2 CTAs/SM

__device__ float g_xv[(size_t)BB * NN * 20];               // variant table 10.5 MB
__device__ __align__(16) unsigned short g_Whi[OUTD * C2];  // swizzled W images
__device__ __align__(16) unsigned short g_Wlo[OUTD * C2];

// ---------------- helpers ----------------
__device__ __forceinline__ unsigned smem_u32(const void* p) {
    unsigned a;
    asm("{ .reg .u64 t; cvta.to.shared.u64 t, %1; cvt.u32.u64 %0, t; }" : "=r"(a) : "l"(p));
    return a;
}
__device__ __forceinline__ void ldsm4(unsigned* r, unsigned addr) {
    asm volatile("ldmatrix.sync.aligned.m8n8.x4.shared.b16 {%0,%1,%2,%3}, [%4];"
                 : "=r"(r[0]), "=r"(r[1]), "=r"(r[2]), "=r"(r[3]) : "r"(addr));
}
__device__ __forceinline__ void mma16816(float* d, const unsigned* a,
                                         unsigned b0, unsigned b1) {
    asm volatile(
        "mma.sync.aligned.m16n8k16.row.col.f32.bf16.bf16.f32 "
        "{%0,%1,%2,%3}, {%4,%5,%6,%7}, {%8,%9}, {%0,%1,%2,%3};"
        : "+f"(d[0]), "+f"(d[1]), "+f"(d[2]), "+f"(d[3])
        : "r"(a[0]), "r"(a[1]), "r"(a[2]), "r"(a[3]), "r"(b0), "r"(b1));
}
__device__ __forceinline__ unsigned pack_hi(float a, float b, float& ra, float& rb) {
    __nv_bfloat16 ha = __float2bfloat16(a), hb = __float2bfloat16(b);
    ra = a - __bfloat162float(ha);
    rb = b - __bfloat162float(hb);
    return ((unsigned)__bfloat16_as_ushort(hb) << 16) | (unsigned)__bfloat16_as_ushort(ha);
}
__device__ __forceinline__ unsigned pack_lo(float ra, float rb) {
    __nv_bfloat16 la = __float2bfloat16(ra);
    __nv_bfloat16 lb = __float2bfloat16(rb);
    return ((unsigned)__bfloat16_as_ushort(lb) << 16) | (unsigned)__bfloat16_as_ushort(la);
}
__device__ __forceinline__ unsigned swz(int r, int k) {
    return (unsigned)(r * ROWB + (((k & 8) | ((k ^ r) & 7)) << 4));
}

// ---------------- prep 1: window-variant table, smem-staged & coalesced --------
__global__ __launch_bounds__(256)
void edgeconv_xv_kernel(const float* __restrict__ x)
{
    __shared__ float s4[64 * 16];
    const int tid = threadIdx.x;
    const int R0  = blockIdx.x * 64;

    const float4* __restrict__ x4 = (const float4*)x + (size_t)R0 * 16;
    #pragma unroll
    for (int i = 0; i < 4; ++i) {
        int idx = tid + 256 * i;
        float4 v = x4[idx];
        s4[idx] = (v.x + v.y) + (v.z + v.w);
    }
    __syncthreads();

    #pragma unroll
    for (int pass = 0; pass < 2; ++pass) {
        int item = tid + pass * 256;
        if (item < 320) {
            int r = item / 5;
            int v = item - 5 * r;
            const float* s = &s4[r * 16];
            const int i1 = 4 - v, i2 = 9 - v, i3 = 14 - v;
            float cum = 0.0f, P1 = 0.0f, P2 = 0.0f, P3 = 0.0f;
            #pragma unroll
            for (int i = 0; i < 16; ++i) {
                cum += s[i];
                if (i == i1) P1 = cum;
                if (i == i2) P2 = cum;
                if (i == i3) P3 = cum;
            }
            float4 o;
            o.x = P1;
            o.y = P2 - P1;
            o.z = P3 - P2;
            o.w = cum - P3;
            *(float4*)&g_xv[(size_t)(R0 + r) * 20 + 4 * v] = o;
        }
    }
}

// ---------------- prep 2: combined weights -> bf16 hi/lo swizzled images ----
__global__ void edgeconv_prepw_kernel(const float* __restrict__ W)
{
    int i = blockIdx.x * blockDim.x + threadIdx.x;
    if (i < OUTD * C2) {
        int o = i >> 7, cc = i & 127;
        float w = W[o * C2 + cc];
        if (cc < CC) w *= (1.0f / (float)KK);
        else         w -= W[o * C2 + (cc - CC)];
        __nv_bfloat16 h = __float2bfloat16(w);
        __nv_bfloat16 l = __float2bfloat16(w - __bfloat162float(h));
        unsigned byteoff = swz(o, cc >> 3) + ((cc & 7) << 1);
        g_Whi[byteoff >> 1] = __bfloat16_as_ushort(h);
        g_Wlo[byteoff >> 1] = __bfloat16_as_ushort(l);
    }
}

// ---------------- main fused kernel ----------------
__global__ __launch_bounds__(THREADS, 2)
void edgeconv_fused_kernel(const float* __restrict__ x,
                           const int* __restrict__ adj,
                           const float* __restrict__ bias,
                           float* __restrict__ out)
{
    extern __shared__ __align__(16) char smem[];
    const unsigned smem_base = smem_u32(smem);

    const int tid = threadIdx.x;
    const int wid = tid >> 5;
    const int lid = tid & 31;
    const int gp0 = blockIdx.x * TP;
    const int b   = gp0 >> 15;
    const int n0  = gp0 & (NN - 1);

    // ---- copy prepped W images + bias; zero scatter planes ----
    {
        const uint4* sh = (const uint4*)g_Whi;
        const uint4* sl = (const uint4*)g_Wlo;
        uint4* dh = (uint4*)(smem + OFF_W_HI);
        uint4* dl = (uint4*)(smem + OFF_W_LO);
        #pragma unroll
        for (int i = tid; i < (OUTD * C2) / 8; i += THREADS) { dh[i] = sh[i]; dl[i] = sl[i]; }
    }
    if (tid < OUTD) ((float*)(smem + OFF_BIAS))[tid] = bias[tid];

    float* __restrict__ sw = (float*)(smem + OFF_SCR) + wid * 256;
    #pragma unroll
    for (int i = lid; i < 256; i += 32) sw[i] = 0.0f;   // plane B stays 0 where unused
    __syncwarp();

    // ---- gather: warp owns points [16*wid, 16*wid+16), processed in pairs ----
    const float4* __restrict__ xv4 = (const float4*)g_xv + (size_t)b * NN * 5;
    const float2* __restrict__ xb2 = (const float2*)(x + (size_t)b * NN * CC);

    const bool act = (lid < KK);
    const int  vS  = act ? (lid % 5) : 0;
    const int  c0  = act ? ((16 * lid - vS) / 5) : 0;     // first window of slot
    const int  a3  = ((vS == 4) ? 0 : 64) + c0 + 3;       // k=3 target (A or B plane)

    int a[16];
    #pragma unroll
    for (int pi = 0; pi < 16; ++pi) {
        int gp = gp0 + 16 * wid + pi;
        a[pi] = act ? adj[(size_t)gp * KK + lid] : 0;
    }

    // prime the pipeline with pair 0
    float4 f0 = make_float4(0.f, 0.f, 0.f, 0.f);
    float4 f1 = make_float4(0.f, 0.f, 0.f, 0.f);
    if (act) {
        f0 = xv4[(size_t)a[0] * 5 + vS];
        f1 = xv4[(size_t)a[1] * 5 + vS];
    }
    float2 xc0 = xb2[(size_t)(n0 + 16 * wid + 0) * 32 + lid];
    float2 xc1 = xb2[(size_t)(n0 + 16 * wid + 1) * 32 + lid];

    #pragma unroll 1
    for (int pi = 0; pi < 16; pi += 2) {
        const int p = 16 * wid + pi;
        float* buf0 = sw;
        float* buf1 = sw + 128;

        if (act) {
            buf0[c0]     = f0.x;
            buf0[c0 + 1] = f0.y;
            buf0[c0 + 2] = f0.z;
            buf0[a3]     = f0.w;
            buf1[c0]     = f1.x;
            buf1[c0 + 1] = f1.y;
            buf1[c0 + 2] = f1.z;
            buf1[a3]     = f1.w;
        }

        // prefetch next pair (full-iteration lead: 4 scattered LDGs in flight)
        float4 fn0 = make_float4(0.f, 0.f, 0.f, 0.f);
        float4 fn1 = make_float4(0.f, 0.f, 0.f, 0.f);
        float2 xn0 = make_float2(0.f, 0.f);
        float2 xn1 = make_float2(0.f, 0.f);
        if (pi < 14) {
            if (act) {
                fn0 = xv4[(size_t)a[pi + 2] * 5 + vS];
                fn1 = xv4[(size_t)a[pi + 3] * 5 + vS];
            }
            xn0 = xb2[(size_t)(n0 + p + 2) * 32 + lid];
            xn1 = xb2[(size_t)(n0 + p + 3) * 32 + lid];
        }

        __syncwarp();

        // read both points' windows
        float2 ga0 = *(const float2*)&buf0[2 * lid];
        float2 gb0 = *(const float2*)&buf0[64 + 2 * lid];
        float2 ga1 = *(const float2*)&buf1[2 * lid];
        float2 gb1 = *(const float2*)&buf1[64 + 2 * lid];
        float wA0 = ga0.x + gb0.x, wB0 = ga0.y + gb0.y;
        float wA1 = ga1.x + gb1.x, wB1 = ga1.y + gb1.y;

        // pack + store A images for point p
        {
            float rg0, rg1, rx0, rx1;
            unsigned hp_g = pack_hi(wA0, wB0, rg0, rg1);
            unsigned hp_x = pack_hi(xc0.x, xc0.y, rx0, rx1);
            unsigned lp_g = pack_lo(rg0, rg1);
            unsigned lp_x = pack_lo(rx0, rx1);
            const int w4 = (lid & 3) << 2;
            unsigned offg = swz(p, lid >> 2)       + w4;
            unsigned offx = swz(p, 8 + (lid >> 2)) + w4;
            *(unsigned*)(smem + OFF_A_HI + offg) = hp_g;
            *(unsigned*)(smem + OFF_A_LO + offg) = lp_g;
            *(unsigned*)(smem + OFF_A_HI + offx) = hp_x;
            *(unsigned*)(smem + OFF_A_LO + offx) = lp_x;
        }
        // point p+1
        {
            float rg0, rg1, rx0, rx1;
            unsigned hp_g = pack_hi(wA1, wB1, rg0, rg1);
            unsigned hp_x = pack_hi(xc1.x, xc1.y, rx0, rx1);
            unsigned lp_g = pack_lo(rg0, rg1);
            unsigned lp_x = pack_lo(rx0, rx1);
            const int w4 = (lid & 3) << 2;
            unsigned offg = swz(p + 1, lid >> 2)       + w4;
            unsigned offx = swz(p + 1, 8 + (lid >> 2)) + w4;
            *(unsigned*)(smem + OFF_A_HI + offg) = hp_g;
            *(unsigned*)(smem + OFF_A_LO + offg) = lp_g;
            *(unsigned*)(smem + OFF_A_HI + offx) = hp_x;
            *(unsigned*)(smem + OFF_A_LO + offx) = lp_x;
        }

        __syncwarp();   // WAR: planes reused next iteration

        f0 = fn0; f1 = fn1; xc0 = xn0; xc1 = xn1;
    }

    __syncthreads();

    // ---- GEMM: warps 4M x 2N, warp tile 32x32, K=128, bf16 3-product split ----
    const int mg = wid & 3;
    const int ng = wid >> 2;
    const int lrow  = (lid & 7) + 8 * ((lid >> 3) & 1);
    const int khalf = lid >> 4;

    const int rA0 = 32 * mg + lrow;
    const int rB0 = 32 * ng + (lid & 15);

    float d[2][4][4];
    #pragma unroll
    for (int mt = 0; mt < 2; ++mt)
        #pragma unroll
        for (int nt = 0; nt < 4; ++nt)
            #pragma unroll
            for (int e = 0; e < 4; ++e) d[mt][nt][e] = 0.0f;

    #pragma unroll 2
    for (int ks = 0; ks < 8; ++ks) {
        const int k = 2 * ks + khalf;
        const unsigned a0 = smem_base + OFF_A_HI + swz(rA0, k);
        const unsigned a1 = smem_base + OFF_A_HI + swz(rA0 + 16, k);
        const unsigned b0 = smem_base + OFF_W_HI + swz(rB0, k);
        const unsigned b1 = smem_base + OFF_W_HI + swz(rB0 + 16, k);

        unsigned ah[2][4], al[2][4];
        ldsm4(ah[0], a0);
        ldsm4(ah[1], a1);
        ldsm4(al[0], a0 + (OFF_A_LO - OFF_A_HI));
        ldsm4(al[1], a1 + (OFF_A_LO - OFF_A_HI));

        unsigned bh01[4], bh23[4], bl01[4], bl23[4];
        ldsm4(bh01, b0);
        ldsm4(bh23, b1);
        ldsm4(bl01, b0 + (OFF_W_LO - OFF_W_HI));
        ldsm4(bl23, b1 + (OFF_W_LO - OFF_W_HI));

        unsigned bhf[4][2] = {{bh01[0], bh01[2]}, {bh01[1], bh01[3]},
                              {bh23[0], bh23[2]}, {bh23[1], bh23[3]}};
        unsigned blf[4][2] = {{bl01[0], bl01[2]}, {bl01[1], bl01[3]},
                              {bl23[0], bl23[2]}, {bl23[1], bl23[3]}};

        #pragma unroll
        for (int mt = 0; mt < 2; ++mt) {
            #pragma unroll
            for (int nt = 0; nt < 4; ++nt) {
                mma16816(d[mt][nt], ah[mt], bhf[nt][0], bhf[nt][1]);
                mma16816(d[mt][nt], al[mt], bhf[nt][0], bhf[nt][1]);
                mma16816(d[mt][nt], ah[mt], blf[nt][0], blf[nt][1]);
            }
        }
    }

    // ---- epilogue: bias + store ----
    const float* sBias = (const float*)(smem + OFF_BIAS);
    const int g  = lid >> 2;
    const int oc = 2 * (lid & 3);
    #pragma unroll
    for (int mt = 0; mt < 2; ++mt) {
        const int prow = gp0 + 32 * mg + 16 * mt + g;
        #pragma unroll
        for (int nt = 0; nt < 4; ++nt) {
            const int o = 32 * ng + 8 * nt + oc;
            float2 bb = *(const float2*)&sBias[o];
            float2 r0, r1;
            r0.x = d[mt][nt][0] + bb.x;  r0.y = d[mt][nt][1] + bb.y;
            r1.x = d[mt][nt][2] + bb.x;  r1.y = d[mt][nt][3] + bb.y;
            *(float2*)&out[(size_t)prow * OUTD + o]       = r0;
            *(float2*)&out[(size_t)(prow + 8) * OUTD + o] = r1;
        }
    }
}

extern "C" void kernel_launch(void* const* d_in, const int* in_sizes, int n_in,
                              void* d_out, int out_size)
{
    (void)in_sizes; (void)n_in; (void)out_size;
    const float* x    = (const float*)d_in[0];
    const int*   adj  = (const int*)d_in[1];
    const float* W    = (const float*)d_in[2];
    const float* bias = (const float*)d_in[3];
    float* out = (float*)d_out;

    cudaFuncSetAttribute(edgeconv_fused_kernel,
                         cudaFuncAttributeMaxDynamicSharedMemorySize, SMEM_BYTES);

    edgeconv_xv_kernel<<<(BB * NN) / 64, 256>>>(x);
    edgeconv_prepw_kernel<<<32, 256>>>(W);
    const int tiles = (BB * NN) / TP;   // 1024
    edgeconv_fused_kernel<<<tiles, THREADS, SMEM_BYTES>>>(x, adj, bias, out);
}